// round 10
// baseline (speedup 1.0000x reference)
#include <cuda_runtime.h>
#include <cstdint>
#include <cstddef>

#define BB 32
#define SS 576
#define DD 768
#define HH 12
#define HDD 64
#define MTOK (BB*SS)               // 18432
#define OUT_ELEMS (BB*SS*DD)       // 14155776
#define ATTN_ELEMS (BB*HH*SS*SS)   // 127401984
#define SCALE 0.125f

// ---- scratch (static device globals; no runtime allocation) ----
__device__ float g_q[OUT_ELEMS];
__device__ float g_k[OUT_ELEMS];
__device__ float g_v[OUT_ELEMS];
__device__ float g_ctx[OUT_ELEMS];
__device__ float g_xr[OUT_ELEMS];
__device__ float g_wq[DD*DD], g_wk[DD*DD], g_wv[DD*DD], g_wo[DD*DD];
__device__ float g_attn_fallback[ATTN_ELEMS];

// ---------------------------------------------------------------------------
__device__ __forceinline__ float rna_tf32(float x) {
    unsigned u;
    asm("cvt.rna.tf32.f32 %0, %1;" : "=r"(u) : "f"(x));
    return __uint_as_float(u);
}

__device__ __forceinline__ void mma_tf32(float c[4],
    uint32_t a0, uint32_t a1, uint32_t a2, uint32_t a3,
    uint32_t b0, uint32_t b1)
{
    asm volatile(
        "mma.sync.aligned.m16n8k8.row.col.f32.tf32.tf32.f32 "
        "{%0,%1,%2,%3}, {%4,%5,%6,%7}, {%8,%9}, {%0,%1,%2,%3};"
        : "+f"(c[0]), "+f"(c[1]), "+f"(c[2]), "+f"(c[3])
        : "r"(a0), "r"(a1), "r"(a2), "r"(a3), "r"(b0), "r"(b1));
}

__device__ __forceinline__ void ldsm_x4(uint32_t& r0, uint32_t& r1,
                                        uint32_t& r2, uint32_t& r3,
                                        const void* p)
{
    uint32_t a = (uint32_t)__cvta_generic_to_shared(p);
    asm volatile("ldmatrix.sync.aligned.m8n8.x4.shared.b16 {%0,%1,%2,%3}, [%4];"
                 : "=r"(r0), "=r"(r1), "=r"(r2), "=r"(r3) : "r"(a));
}

__device__ __forceinline__ void cpa16(void* dst, const void* src) {
    uint32_t d = (uint32_t)__cvta_generic_to_shared(dst);
    asm volatile("cp.async.cg.shared.global [%0], [%1], 16;\n"
                 :: "r"(d), "l"(src));
}
#define CP_COMMIT() asm volatile("cp.async.commit_group;\n" ::)
#define CP_WAIT0()  asm volatile("cp.async.wait_group 0;\n" ::)
#define CP_WAIT1()  asm volatile("cp.async.wait_group 1;\n" ::)

// ---------------------------------------------------------------------------
__global__ void round_tf32_kernel(const float* __restrict__ in,
                                  float* __restrict__ out, int n4)
{
    for (int i = blockIdx.x * blockDim.x + threadIdx.x; i < n4;
         i += gridDim.x * blockDim.x) {
        float4 v = ((const float4*)in)[i];
        v.x = rna_tf32(v.x); v.y = rna_tf32(v.y);
        v.z = rna_tf32(v.z); v.w = rna_tf32(v.w);
        ((float4*)out)[i] = v;
    }
}

__global__ void round_w4_kernel(
    const float* __restrict__ w0, const float* __restrict__ w1,
    const float* __restrict__ w2, const float* __restrict__ w3,
    float* __restrict__ o0, float* __restrict__ o1,
    float* __restrict__ o2, float* __restrict__ o3, int n4)
{
    int z = blockIdx.y;
    const float* in = (z == 0) ? w0 : (z == 1) ? w1 : (z == 2) ? w2 : w3;
    float* out      = (z == 0) ? o0 : (z == 1) ? o1 : (z == 2) ? o2 : o3;
    for (int i = blockIdx.x * blockDim.x + threadIdx.x; i < n4;
         i += gridDim.x * blockDim.x) {
        float4 v = ((const float4*)in)[i];
        v.x = rna_tf32(v.x); v.y = rna_tf32(v.y);
        v.z = rna_tf32(v.z); v.w = rna_tf32(v.w);
        ((float4*)out)[i] = v;
    }
}

// ---------------------------------------------------------------------------
// GEMM: C[M,N] = A[M,K] @ W^T + bias.  A,W pre-rounded to tf32.
// BM=128, BN=128, BK=48 (16 iters), 256 threads, ldmatrix fragment loads,
// 2-stage cp.async pipeline (sync-before-issue).  Stride 52 floats.
// ---------------------------------------------------------------------------
#define GSTR 52
#define GST (2*128*GSTR)   // floats per stage (A+B) = 13312

template <bool RND>
__device__ __forceinline__ void gemm_body(
    const float* __restrict__ A, const float* __restrict__ W,
    const float* __restrict__ bias, float* __restrict__ C,
    int N, int K)
{
    extern __shared__ float dsm[];

    const int tid = threadIdx.x;
    const int m0 = blockIdx.y * 128;
    const int n0 = blockIdx.x * 128;
    const int warp = tid >> 5;
    const int lane = tid & 31;
    const int g = lane >> 2;
    const int t = lane & 3;
    const int warpm = warp >> 2;  // 0..1
    const int warpn = warp & 3;   // 0..3

    const int laneA = (lane & 15) * GSTR + ((lane >> 4) << 2);
    const int laneB = (((lane >> 4) << 3) + (lane & 7)) * GSTR + (((lane >> 3) & 1) << 2);

    float acc[4][4][4];
    #pragma unroll
    for (int i = 0; i < 4; i++)
        #pragma unroll
        for (int j = 0; j < 4; j++)
            #pragma unroll
            for (int r = 0; r < 4; r++) acc[i][j][r] = 0.f;

    const int row = tid >> 1;
    const int half = tid & 1;

    auto load_stage = [&](int st, int k0) {
        float* as = dsm + st * GST;
        float* bs = as + 128*GSTR;
        #pragma unroll
        for (int i = 0; i < 6; i++) {
            int seg = half*6 + i;
            cpa16(&as[row*GSTR + seg*4], &A[(size_t)(m0 + row) * K + k0 + seg*4]);
        }
        #pragma unroll
        for (int i = 0; i < 6; i++) {
            int seg = half*6 + i;
            cpa16(&bs[row*GSTR + seg*4], &W[(size_t)(n0 + row) * K + k0 + seg*4]);
        }
    };

    const int iters = K / 48;            // 16
    load_stage(0, 0);  CP_COMMIT();

    for (int it = 0; it < iters; ++it) {
        __syncthreads();                         // buf (it+1)&1 readers done
        if (it + 1 < iters) load_stage((it + 1) & 1, (it + 1) * 48);
        CP_COMMIT();
        CP_WAIT1();                              // stage it ready (own copies)
        __syncthreads();                         // all threads' copies visible

        const float* as = dsm + (it & 1) * GST;
        const float* bs = as + 128*GSTR;
        #pragma unroll
        for (int ks = 0; ks < 6; ks++) {
            int k = ks * 8;
            uint32_t af[4][4];
            #pragma unroll
            for (int ms = 0; ms < 4; ms++)
                ldsm_x4(af[ms][0], af[ms][1], af[ms][2], af[ms][3],
                        as + (warpm*64 + ms*16)*GSTR + k + laneA);
            #pragma unroll
            for (int pr = 0; pr < 2; pr++) {
                uint32_t b0, b1, b2, b3;
                ldsm_x4(b0, b1, b2, b3,
                        bs + (warpn*32 + pr*16)*GSTR + k + laneB);
                #pragma unroll
                for (int ms = 0; ms < 4; ms++) {
                    mma_tf32(acc[ms][2*pr],   af[ms][0], af[ms][1], af[ms][2],
                             af[ms][3], b0, b1);
                    mma_tf32(acc[ms][2*pr+1], af[ms][0], af[ms][1], af[ms][2],
                             af[ms][3], b2, b3);
                }
            }
        }
    }

    #pragma unroll
    for (int ms = 0; ms < 4; ms++) {
        int row0 = m0 + warpm*64 + ms*16 + g;
        #pragma unroll
        for (int ns = 0; ns < 4; ns++) {
            int col = n0 + warpn*32 + ns*8 + 2*t;
            float b0v = bias[col], b1v = bias[col + 1];
            float2 v0, v1;
            if (RND) {
                v0 = {rna_tf32(acc[ms][ns][0] + b0v), rna_tf32(acc[ms][ns][1] + b1v)};
                v1 = {rna_tf32(acc[ms][ns][2] + b0v), rna_tf32(acc[ms][ns][3] + b1v)};
            } else {
                v0 = {acc[ms][ns][0] + b0v, acc[ms][ns][1] + b1v};
                v1 = {acc[ms][ns][2] + b0v, acc[ms][ns][3] + b1v};
            }
            *(float2*)&C[(size_t)row0 * N + col] = v0;
            *(float2*)&C[(size_t)(row0 + 8) * N + col] = v1;
        }
    }
}

__global__ __launch_bounds__(256) void gemm_qkv(
    const float* __restrict__ A,
    const float* __restrict__ Wq, const float* __restrict__ Wk,
    const float* __restrict__ Wv,
    const float* __restrict__ bq, const float* __restrict__ bk,
    const float* __restrict__ bv,
    float* __restrict__ Cq, float* __restrict__ Ck, float* __restrict__ Cv)
{
    int z = blockIdx.z;
    const float* W    = (z == 0) ? Wq : (z == 1) ? Wk : Wv;
    const float* bias = (z == 0) ? bq : (z == 1) ? bk : bv;
    float*       C    = (z == 0) ? Cq : (z == 1) ? Ck : Cv;
    gemm_body<true>(A, W, bias, C, DD, DD);
}

__global__ __launch_bounds__(256) void gemm_single(
    const float* __restrict__ A, const float* __restrict__ W,
    const float* __restrict__ bias, float* __restrict__ C)
{
    gemm_body<false>(A, W, bias, C, DD, DD);
}

// ---------------------------------------------------------------------------
// Fused attention per (b, h, 32-query tile).
// scores: 64-key stages, 8 warps = 8 distinct key-slices (K read exactly 1x),
//         Q register-resident (loaded via strip region, then dead).
// softmax: register-resident rows.
// AV: prob frags via ldmatrix.x4; warp grid (Nm,Nn,Nk)=(1,2,4);
//     4 k-partials reduced through smem; ctx float4.
// smem: kvb[2][64*68] + sc[32][580] = 109056 B -> 2 CTA/SM.
// ---------------------------------------------------------------------------
#define SCQ 68
#define SCK 68
#define VSS 72
#define K64PITCH (64*SCK)   // 4352 floats per K stage
#define V32PITCH (32*VSS)   // 2304 floats per V stage
#define SCS 580
#define QROWS 32
#define NST64 (SS/64)   // 9
#define NSTV (SS/32)    // 18
#define RST 72
#define ATTN_SMEM_FLOATS (2*K64PITCH + QROWS*SCS)  // 27264

__global__ __launch_bounds__(256, 2) void attn_fused(
    const float* __restrict__ Q, const float* __restrict__ K,
    const float* __restrict__ V, float* __restrict__ attn,
    float* __restrict__ ctx)
{
    extern __shared__ float smem[];
    float* kvb = smem;                    // K: 2x[64][SCK]; V: 2x[32][VSS]
    float* sc  = smem + 2*K64PITCH;       // [32][SCS]; Q tile parks here first

    const int qt = blockIdx.x, h = blockIdx.y, b = blockIdx.z;
    const int s0 = qt * QROWS;
    const int tid = threadIdx.x;
    const int warp = tid >> 5;
    const int lane = tid & 31;
    const int g = lane >> 2, t = lane & 3;

    const size_t kvbase = (size_t)b * SS * DD + h * HDD;

    auto load_q = [&]() {   // Q tile -> strip region, stride SCQ
        #pragma unroll
        for (int i = 0; i < 2; i++) {
            int c = tid + i * 256;
            int qi = c >> 4, seg = c & 15;
            cpa16(&sc[qi*SCQ + seg*4],
                  &Q[kvbase + (size_t)(s0 + qi)*DD + seg*4]);
        }
    };
    auto load_k64 = [&](int st, int kt) {   // 64 keys
        float* dst = kvb + st * K64PITCH;
        #pragma unroll
        for (int i = 0; i < 4; i++) {
            int c = tid + i * 256;
            int row = c >> 4, seg = c & 15;
            cpa16(&dst[row*SCK + seg*4],
                  &K[kvbase + (size_t)(kt*64 + row)*DD + seg*4]);
        }
    };
    auto load_v = [&](int st, int kt) {     // 32 keys
        float* dst = kvb + st * V32PITCH;
        #pragma unroll
        for (int i = 0; i < 2; i++) {
            int c = tid + i * 256;
            int row = c >> 4, seg = c & 15;
            cpa16(&dst[row*VSS + seg*4],
                  &V[kvbase + (size_t)(kt*32 + row)*DD + seg*4]);
        }
    };

    // Q + K stage 0 (one group)
    load_q(); load_k64(0, 0); CP_COMMIT();
    CP_WAIT0();
    __syncthreads();

    // hoist Q fragments: all warps need rows 0..31 (m=32 per warp)
    uint32_t qa[2][8][4];
    #pragma unroll
    for (int ms = 0; ms < 2; ms++)
        #pragma unroll
        for (int kk = 0; kk < 8; kk++) {
            const float* pa = sc + (ms*16 + g)*SCQ + kk*8 + t;
            qa[ms][kk][0] = __float_as_uint(pa[0]);
            qa[ms][kk][1] = __float_as_uint(pa[8*SCQ]);
            qa[ms][kk][2] = __float_as_uint(pa[4]);
            qa[ms][kk][3] = __float_as_uint(pa[8*SCQ + 4]);
        }
    __syncthreads();   // all hoists done before strip writes overwrite Q

    // K-frag ldmatrix lane offset (x4 = 8 keys x 2 k-steps)
    const int laneKB = (lane & 7) * SCK + ((lane >> 3) << 2);
    // AV prob-frag lane offset
    const int laneAS = (lane & 15) * SCS + ((lane >> 4) << 2);

    // ---- scores: 9 x 64-key stages; warp owns keys [warp*8, warp*8+8) ----
    for (int kt = 0; kt < NST64; kt++) {
        if (kt > 0) __syncthreads();     // buf (kt+1)&1 readers done
        if (kt + 1 < NST64) load_k64((kt + 1) & 1, kt + 1);
        CP_COMMIT();
        CP_WAIT1();                      // own stage-kt copies done
        if (kt > 0) __syncthreads();     // all copies visible (kt=0: earlier)

        const float* ks = kvb + (kt & 1) * K64PITCH;
        float acc[2][4];
        #pragma unroll
        for (int ms = 0; ms < 2; ms++)
            #pragma unroll
            for (int r = 0; r < 4; r++) acc[ms][r] = 0.f;

        #pragma unroll
        for (int kk2 = 0; kk2 < 4; kk2++) {
            uint32_t b0, b1, b2, b3;
            ldsm_x4(b0, b1, b2, b3, ks + warp*8*SCK + kk2*16 + laneKB);
            #pragma unroll
            for (int ms = 0; ms < 2; ms++) {
                mma_tf32(acc[ms], qa[ms][2*kk2][0], qa[ms][2*kk2][1],
                         qa[ms][2*kk2][2], qa[ms][2*kk2][3], b0, b1);
                mma_tf32(acc[ms], qa[ms][2*kk2+1][0], qa[ms][2*kk2+1][1],
                         qa[ms][2*kk2+1][2], qa[ms][2*kk2+1][3], b2, b3);
            }
        }

        #pragma unroll
        for (int ms = 0; ms < 2; ms++) {
            int row = ms*16 + g;
            int col = kt*64 + warp*8 + 2*t;
            float2 v0 = {acc[ms][0]*SCALE, acc[ms][1]*SCALE};
            *(float2*)&sc[row*SCS + col] = v0;
            float2 v1 = {acc[ms][2]*SCALE, acc[ms][3]*SCALE};
            *(float2*)&sc[(row+8)*SCS + col] = v1;
        }
    }
    __syncthreads();

    // prefetch V stage 0 -> overlaps softmax
    load_v(0, 0); CP_COMMIT();

    // ---- softmax: 8 warps x 4 rows, register-resident ----
    #pragma unroll
    for (int rr = 0; rr < 4; rr++) {
        const int r = warp*4 + rr;
        float ev[18];
        #pragma unroll
        for (int jj = 0; jj < 18; jj++) ev[jj] = sc[r*SCS + lane + 32*jj];
        float mx = ev[0];
        #pragma unroll
        for (int jj = 1; jj < 18; jj++) mx = fmaxf(mx, ev[jj]);
        #pragma unroll
        for (int o = 16; o; o >>= 1) mx = fmaxf(mx, __shfl_xor_sync(0xffffffffu, mx, o));
        float sum = 0.f;
        #pragma unroll
        for (int jj = 0; jj < 18; jj++) {
            ev[jj] = __expf(ev[jj] - mx);
            sum += ev[jj];
        }
        #pragma unroll
        for (int o = 16; o; o >>= 1) sum += __shfl_xor_sync(0xffffffffu, sum, o);
        float inv = 1.f / sum;
        float* dst = attn + (((size_t)b*HH + h)*SS + s0 + r) * (size_t)SS;
        #pragma unroll
        for (int jj = 0; jj < 18; jj++) {
            float p = ev[jj] * inv;
            dst[lane + 32*jj] = p;
            sc[r*SCS + lane + 32*jj] = rna_tf32(p);
        }
    }
    __syncthreads();

    // ---- AV: (Nm,Nn,Nk)=(1,2,4), 18 x 32-key stages, 2 buffers ----
    const int wn = warp & 1;
    const int wk = warp >> 1;

    float acc[2][4][4];
    #pragma unroll
    for (int i = 0; i < 2; i++)
        #pragma unroll
        for (int j = 0; j < 4; j++)
            #pragma unroll
            for (int r = 0; r < 4; r++) acc[i][j][r] = 0.f;

    for (int kt = 0; kt < NSTV; kt++) {
        if (kt > 0) __syncthreads();     // buf (kt+1)&1 readers done
        if (kt + 1 < NSTV) load_v((kt + 1) & 1, kt + 1);
        CP_COMMIT();
        CP_WAIT1();                      // own stage-kt copies done
        __syncthreads();                 // ALL threads' stage-kt copies visible

        const float* vs = kvb + (kt & 1) * V32PITCH;
        const int k = wk * 8;

        uint32_t a[2][4];
        #pragma unroll
        for (int ms = 0; ms < 2; ms++)
            ldsm_x4(a[ms][0], a[ms][1], a[ms][2], a[ms][3],
                    sc + ms*16*SCS + kt*32 + k + laneAS);
        #pragma unroll
        for (int ns = 0; ns < 4; ns++) {
            int nb = wn*32 + ns*8;
            uint32_t b0 = __float_as_uint(vs[(k + t)*VSS + nb + g]);
            uint32_t b1 = __float_as_uint(vs[(k + t + 4)*VSS + nb + g]);
            #pragma unroll
            for (int ms = 0; ms < 2; ms++)
                mma_tf32(acc[ms][ns], a[ms][0], a[ms][1], a[ms][2], a[ms][3],
                         b0, b1);
        }
    }

    // ---- reduce 4 k-partials through smem (strip region reused) ----
    __syncthreads();
    float* red = sc;   // [4][32][RST]
    #pragma unroll
    for (int ms = 0; ms < 2; ms++) {
        #pragma unroll
        for (int ns = 0; ns < 4; ns++) {
            int col = wn*32 + ns*8 + 2*t;
            float2 v0 = {acc[ms][ns][0], acc[ms][ns][1]};
            *(float2*)&red[wk*32*RST + (ms*16 + g)*RST + col] = v0;
            float2 v1 = {acc[ms][ns][2], acc[ms][ns][3]};
            *(float2*)&red[wk*32*RST + (ms*16 + g + 8)*RST + col] = v1;
        }
    }
    __syncthreads();

    #pragma unroll
    for (int i = 0; i < 2; i++) {
        int f4 = tid + i*256;
        int row = f4 >> 4, c4 = f4 & 15;
        const float* p0 = red + row*RST + c4*4;
        float4 s0v = *(const float4*)(p0);
        float4 s1v = *(const float4*)(p0 + 32*RST);
        float4 s2v = *(const float4*)(p0 + 64*RST);
        float4 s3v = *(const float4*)(p0 + 96*RST);
        float4 o;
        o.x = rna_tf32(s0v.x + s1v.x + s2v.x + s3v.x);
        o.y = rna_tf32(s0v.y + s1v.y + s2v.y + s3v.y);
        o.z = rna_tf32(s0v.z + s1v.z + s2v.z + s3v.z);
        o.w = rna_tf32(s0v.w + s1v.w + s2v.w + s3v.w);
        *(float4*)&ctx[((size_t)(b*SS + s0 + row))*DD + h*HDD + c4*4] = o;
    }
}

// ===========================================================================
extern "C" void kernel_launch(void* const* d_in, const int* in_sizes, int n_in,
                              void* d_out, int out_size)
{
    const float* x  = (const float*)d_in[0];
    const float* Wq = (const float*)d_in[1];
    const float* bq = (const float*)d_in[2];
    const float* Wk = (const float*)d_in[3];
    const float* bk = (const float*)d_in[4];
    const float* Wv = (const float*)d_in[5];
    const float* bv = (const float*)d_in[6];
    const float* Wo = (const float*)d_in[7];
    const float* bo = (const float*)d_in[8];

    float* out = (float*)d_out;
    float* attn;
    if (out_size >= OUT_ELEMS + ATTN_ELEMS) {
        attn = out + OUT_ELEMS;
    } else {
        void* p; cudaGetSymbolAddress(&p, g_attn_fallback);
        attn = (float*)p;
    }

    float *q, *k, *v, *ctx, *xr, *wq, *wk, *wv, *wo;
    { void* p; cudaGetSymbolAddress(&p, g_q);   q   = (float*)p; }
    { void* p; cudaGetSymbolAddress(&p, g_k);   k   = (float*)p; }
    { void* p; cudaGetSymbolAddress(&p, g_v);   v   = (float*)p; }
    { void* p; cudaGetSymbolAddress(&p, g_ctx); ctx = (float*)p; }
    { void* p; cudaGetSymbolAddress(&p, g_xr);  xr  = (float*)p; }
    { void* p; cudaGetSymbolAddress(&p, g_wq);  wq  = (float*)p; }
    { void* p; cudaGetSymbolAddress(&p, g_wk);  wk  = (float*)p; }
    { void* p; cudaGetSymbolAddress(&p, g_wv);  wv  = (float*)p; }
    { void* p; cudaGetSymbolAddress(&p, g_wo);  wo  = (float*)p; }

    const int gemm_smem = 2 * GST * (int)sizeof(float);          // 106496
    cudaFuncSetAttribute(gemm_qkv,
                         cudaFuncAttributeMaxDynamicSharedMemorySize, gemm_smem);
    cudaFuncSetAttribute(gemm_single,
                         cudaFuncAttributeMaxDynamicSharedMemorySize, gemm_smem);
    const int attn_smem = ATTN_SMEM_FLOATS * (int)sizeof(float); // 109056
    cudaFuncSetAttribute(attn_fused,
                         cudaFuncAttributeMaxDynamicSharedMemorySize, attn_smem);

    // 1) tf32 pre-rounding
    round_tf32_kernel<<<1184, 256>>>(x, xr, OUT_ELEMS/4);
    dim3 gW(288, 4);
    round_w4_kernel<<<gW, 256>>>(Wq, Wk, Wv, Wo, wq, wk, wv, wo, (DD*DD)/4);

    // 2) fused Q/K/V projections (outputs rna-rounded to tf32)
    dim3 gQKV(DD/128, MTOK/128, 3);
    gemm_qkv<<<gQKV, 256, gemm_smem>>>(xr, wq, wk, wv, bq, bk, bv, q, k, v);

    // 3) fused scores + softmax + AV
    dim3 gAttn(SS/QROWS, HH, BB);         // (18, 12, 32)
    attn_fused<<<gAttn, 256, attn_smem>>>(q, k, v, attn, ctx);

    // 4) output projection
    dim3 gO(DD/128, MTOK/128);
    gemm_single<<<gO, 256, gemm_smem>>>(ctx, wo, bo, out);
}

// round 11
// speedup vs baseline: 1.3865x; 1.3865x over previous
#include <cuda_runtime.h>
#include <cstdint>
#include <cstddef>

#define BB 32
#define SS 576
#define DD 768
#define HH 12
#define HDD 64
#define MTOK (BB*SS)               // 18432
#define OUT_ELEMS (BB*SS*DD)       // 14155776
#define ATTN_ELEMS (BB*HH*SS*SS)   // 127401984
#define SCALE 0.125f

// ---- scratch (static device globals; no runtime allocation) ----
__device__ float g_q[OUT_ELEMS];
__device__ float g_k[OUT_ELEMS];
__device__ float g_v[OUT_ELEMS];
__device__ float g_ctx[OUT_ELEMS];
__device__ float g_xr[OUT_ELEMS];
__device__ float g_attn_fallback[ATTN_ELEMS];

// ---------------------------------------------------------------------------
__device__ __forceinline__ float rna_tf32(float x) {
    unsigned u;
    asm("cvt.rna.tf32.f32 %0, %1;" : "=r"(u) : "f"(x));
    return __uint_as_float(u);
}

__device__ __forceinline__ uint32_t rna_bits(uint32_t x) {
    unsigned u;
    asm("cvt.rna.tf32.f32 %0, %1;" : "=r"(u) : "f"(__uint_as_float(x)));
    return u;
}

__device__ __forceinline__ void mma_tf32(float c[4],
    uint32_t a0, uint32_t a1, uint32_t a2, uint32_t a3,
    uint32_t b0, uint32_t b1)
{
    asm volatile(
        "mma.sync.aligned.m16n8k8.row.col.f32.tf32.tf32.f32 "
        "{%0,%1,%2,%3}, {%4,%5,%6,%7}, {%8,%9}, {%0,%1,%2,%3};"
        : "+f"(c[0]), "+f"(c[1]), "+f"(c[2]), "+f"(c[3])
        : "r"(a0), "r"(a1), "r"(a2), "r"(a3), "r"(b0), "r"(b1));
}

__device__ __forceinline__ void ldsm_x4(uint32_t& r0, uint32_t& r1,
                                        uint32_t& r2, uint32_t& r3,
                                        const void* p)
{
    uint32_t a = (uint32_t)__cvta_generic_to_shared(p);
    asm volatile("ldmatrix.sync.aligned.m8n8.x4.shared.b16 {%0,%1,%2,%3}, [%4];"
                 : "=r"(r0), "=r"(r1), "=r"(r2), "=r"(r3) : "r"(a));
}

__device__ __forceinline__ void cpa16(void* dst, const void* src) {
    uint32_t d = (uint32_t)__cvta_generic_to_shared(dst);
    asm volatile("cp.async.cg.shared.global [%0], [%1], 16;\n"
                 :: "r"(d), "l"(src));
}
#define CP_COMMIT() asm volatile("cp.async.commit_group;\n" ::)
#define CP_WAIT1()  asm volatile("cp.async.wait_group 1;\n" ::)
#define CP_WAIT2()  asm volatile("cp.async.wait_group 2;\n" ::)

// ---------------------------------------------------------------------------
__global__ void round_tf32_kernel(const float* __restrict__ in,
                                  float* __restrict__ out, int n4)
{
    for (int i = blockIdx.x * blockDim.x + threadIdx.x; i < n4;
         i += gridDim.x * blockDim.x) {
        float4 v = ((const float4*)in)[i];
        v.x = rna_tf32(v.x); v.y = rna_tf32(v.y);
        v.z = rna_tf32(v.z); v.w = rna_tf32(v.w);
        ((float4*)out)[i] = v;
    }
}

// ---------------------------------------------------------------------------
// GEMM: C[M,N] = A[M,K] @ W^T + bias.  A pre-rounded tf32; W raw fp32,
// rounded (rna) on the B-fragment registers after ldmatrix (bit-identical
// to pre-rounding W).  BM=128, BN=128, BK=32, 256 threads,
// ldmatrix fragment loads, 3-stage cp.async pipeline.
// ---------------------------------------------------------------------------
#define GST (2*128*36)   // floats per stage (A+B)

template <bool RND>
__device__ __forceinline__ void gemm_body(
    const float* __restrict__ A, const float* __restrict__ W,
    const float* __restrict__ bias, float* __restrict__ C,
    int N, int K)
{
    extern __shared__ float dsm[];

    const int tid = threadIdx.x;
    const int m0 = blockIdx.y * 128;
    const int n0 = blockIdx.x * 128;
    const int warp = tid >> 5;
    const int lane = tid & 31;
    const int g = lane >> 2;
    const int t = lane & 3;
    const int warpm = warp >> 2;  // 0..1
    const int warpn = warp & 3;   // 0..3

    const int laneA = (lane & 15) * 36 + ((lane >> 4) << 2);
    const int laneB = (((lane >> 4) << 3) + (lane & 7)) * 36 + (((lane >> 3) & 1) << 2);

    float acc[4][4][4];
    #pragma unroll
    for (int i = 0; i < 4; i++)
        #pragma unroll
        for (int j = 0; j < 4; j++)
            #pragma unroll
            for (int r = 0; r < 4; r++) acc[i][j][r] = 0.f;

    auto load_stage = [&](int st, int k0) {
        float* as = dsm + st * GST;
        float* bs = as + 128*36;
        #pragma unroll
        for (int i = 0; i < 4; i++) {
            int c = tid + i * 256;
            int row = c >> 3, seg = c & 7;
            cpa16(&as[row*36 + seg*4], &A[(size_t)(m0 + row) * K + k0 + seg*4]);
        }
        #pragma unroll
        for (int i = 0; i < 4; i++) {
            int c = tid + i * 256;
            int row = c >> 3, seg = c & 7;
            cpa16(&bs[row*36 + seg*4], &W[(size_t)(n0 + row) * K + k0 + seg*4]);
        }
    };

    const int iters = K / 32;            // 24
    load_stage(0, 0);  CP_COMMIT();
    load_stage(1, 32); CP_COMMIT();

    for (int it = 0; it < iters; ++it) {
        CP_WAIT1();
        __syncthreads();
        if (it + 2 < iters) load_stage((it + 2) % 3, (it + 2) * 32);
        CP_COMMIT();

        const float* as = dsm + (it % 3) * GST;
        const float* bs = as + 128*36;
        #pragma unroll
        for (int ks = 0; ks < 4; ks++) {
            int k = ks * 8;
            uint32_t af[4][4];
            #pragma unroll
            for (int ms = 0; ms < 4; ms++)
                ldsm_x4(af[ms][0], af[ms][1], af[ms][2], af[ms][3],
                        as + (warpm*64 + ms*16)*36 + k + laneA);
            #pragma unroll
            for (int pr = 0; pr < 2; pr++) {
                uint32_t b0, b1, b2, b3;
                ldsm_x4(b0, b1, b2, b3,
                        bs + (warpn*32 + pr*16)*36 + k + laneB);
                b0 = rna_bits(b0); b1 = rna_bits(b1);
                b2 = rna_bits(b2); b3 = rna_bits(b3);
                #pragma unroll
                for (int ms = 0; ms < 4; ms++) {
                    mma_tf32(acc[ms][2*pr],   af[ms][0], af[ms][1], af[ms][2],
                             af[ms][3], b0, b1);
                    mma_tf32(acc[ms][2*pr+1], af[ms][0], af[ms][1], af[ms][2],
                             af[ms][3], b2, b3);
                }
            }
        }
        __syncthreads();
    }

    #pragma unroll
    for (int ms = 0; ms < 4; ms++) {
        int row0 = m0 + warpm*64 + ms*16 + g;
        #pragma unroll
        for (int ns = 0; ns < 4; ns++) {
            int col = n0 + warpn*32 + ns*8 + 2*t;
            float b0v = bias[col], b1v = bias[col + 1];
            float2 v0, v1;
            if (RND) {
                v0 = {rna_tf32(acc[ms][ns][0] + b0v), rna_tf32(acc[ms][ns][1] + b1v)};
                v1 = {rna_tf32(acc[ms][ns][2] + b0v), rna_tf32(acc[ms][ns][3] + b1v)};
            } else {
                v0 = {acc[ms][ns][0] + b0v, acc[ms][ns][1] + b1v};
                v1 = {acc[ms][ns][2] + b0v, acc[ms][ns][3] + b1v};
            }
            *(float2*)&C[(size_t)row0 * N + col] = v0;
            *(float2*)&C[(size_t)(row0 + 8) * N + col] = v1;
        }
    }
}

__global__ __launch_bounds__(256) void gemm_qkv(
    const float* __restrict__ A,
    const float* __restrict__ Wq, const float* __restrict__ Wk,
    const float* __restrict__ Wv,
    const float* __restrict__ bq, const float* __restrict__ bk,
    const float* __restrict__ bv,
    float* __restrict__ Cq, float* __restrict__ Ck, float* __restrict__ Cv)
{
    int z = blockIdx.z;
    const float* W    = (z == 0) ? Wq : (z == 1) ? Wk : Wv;
    const float* bias = (z == 0) ? bq : (z == 1) ? bk : bv;
    float*       C    = (z == 0) ? Cq : (z == 1) ? Ck : Cv;
    gemm_body<true>(A, W, bias, C, DD, DD);   // rna-rounded Q/K/V
}

__global__ __launch_bounds__(256) void gemm_single(
    const float* __restrict__ A, const float* __restrict__ W,
    const float* __restrict__ bias, float* __restrict__ C)
{
    gemm_body<false>(A, W, bias, C, DD, DD);
}

// ---------------------------------------------------------------------------
// Fused attention per (b, h, 32-query tile).  (R7 structure — proven.)
// scores: Q frags in registers, K frags via ldmatrix.x4 (2 k-steps per load).
// softmax: register-resident rows; attn written with streaming stores (.cs).
// AV: prob frags via ldmatrix.x4; warp grid (Nm,Nn,Nk)=(1,2,4);
//     4 k-partials reduced through smem; ctx float4.
// smem: qs[32][68] + kv[3][32*72] + sc[32][580] = 110592 B -> 2 CTA/SM.
// ---------------------------------------------------------------------------
#define SCQ 68
#define SCK 68
#define VSS 72
#define KVPITCH (32*72)
#define SCS 580
#define QROWS 32
#define NSTAGE (SS/32)  // 18
#define RST 72
#define ATTN_SMEM_FLOATS (QROWS*SCQ + 3*KVPITCH + QROWS*SCS)  // 27648

__global__ __launch_bounds__(256, 2) void attn_fused(
    const float* __restrict__ Q, const float* __restrict__ K,
    const float* __restrict__ V, float* __restrict__ attn,
    float* __restrict__ ctx)
{
    extern __shared__ float smem[];
    float* qs = smem;                         // [32][SCQ]
    float* kv = smem + QROWS*SCQ;             // 3 stage buffers
    float* sc = smem + QROWS*SCQ + 3*KVPITCH; // [32][SCS]; later red[4][32][RST]

    const int qt = blockIdx.x, h = blockIdx.y, b = blockIdx.z;
    const int s0 = qt * QROWS;
    const int tid = threadIdx.x;
    const int warp = tid >> 5;
    const int lane = tid & 31;
    const int g = lane >> 2, t = lane & 3;

    const size_t kvbase = (size_t)b * SS * DD + h * HDD;

    auto load_q = [&]() {
        #pragma unroll
        for (int i = 0; i < 2; i++) {
            int c = tid + i * 256;
            int qi = c >> 4, seg = c & 15;
            cpa16(&qs[qi*SCQ + seg*4],
                  &Q[kvbase + (size_t)(s0 + qi)*DD + seg*4]);
        }
    };
    auto load_k = [&](int st, int kt) {
        float* dst = kv + st * KVPITCH;
        #pragma unroll
        for (int i = 0; i < 2; i++) {
            int c = tid + i * 256;
            int row = c >> 4, seg = c & 15;
            cpa16(&dst[row*SCK + seg*4],
                  &K[kvbase + (size_t)(kt*32 + row)*DD + seg*4]);
        }
    };
    auto load_v = [&](int st, int kt) {
        float* dst = kv + st * KVPITCH;
        #pragma unroll
        for (int i = 0; i < 2; i++) {
            int c = tid + i * 256;
            int row = c >> 4, seg = c & 15;
            cpa16(&dst[row*VSS + seg*4],
                  &V[kvbase + (size_t)(kt*32 + row)*DD + seg*4]);
        }
    };

    load_q();     CP_COMMIT();
    load_k(0, 0); CP_COMMIT();
    load_k(1, 1); CP_COMMIT();

    // wait for Q group, then hoist Q fragments into registers
    CP_WAIT2();
    __syncthreads();
    const int warpm = warp >> 2;   // scores: 0..1
    const int warpn = warp & 3;    // scores: 0..3
    uint32_t qa[8][4];
    #pragma unroll
    for (int kk = 0; kk < 8; kk++) {
        const float* pa = qs + (warpm*16 + g)*SCQ + kk*8 + t;
        qa[kk][0] = __float_as_uint(pa[0]);
        qa[kk][1] = __float_as_uint(pa[8*SCQ]);
        qa[kk][2] = __float_as_uint(pa[4]);
        qa[kk][3] = __float_as_uint(pa[8*SCQ + 4]);
    }

    const int laneKB = (lane & 7) * SCK + ((lane >> 3) << 2);
    const int laneAS = (lane & 15) * SCS + ((lane >> 4) << 2);

    // ---- scores: QK^T into sc strip, 18 pipelined stages ----
    for (int kt = 0; kt < NSTAGE; kt++) {
        CP_WAIT1();
        __syncthreads();
        if (kt + 2 < NSTAGE) load_k((kt + 2) % 3, kt + 2);
        CP_COMMIT();

        const float* ks = kv + (kt % 3) * KVPITCH;
        float acc[4] = {0.f, 0.f, 0.f, 0.f};
        #pragma unroll
        for (int kk2 = 0; kk2 < 4; kk2++) {
            uint32_t b0, b1, b2, b3;
            ldsm_x4(b0, b1, b2, b3,
                    ks + warpn*8*SCK + kk2*16 + laneKB);
            mma_tf32(acc, qa[2*kk2][0], qa[2*kk2][1], qa[2*kk2][2],
                     qa[2*kk2][3], b0, b1);
            mma_tf32(acc, qa[2*kk2+1][0], qa[2*kk2+1][1], qa[2*kk2+1][2],
                     qa[2*kk2+1][3], b2, b3);
        }

        int row = warpm*16 + g;
        int col = kt*32 + warpn*8 + 2*t;
        float2 v0 = {acc[0]*SCALE, acc[1]*SCALE};
        *(float2*)&sc[row*SCS + col] = v0;
        float2 v1 = {acc[2]*SCALE, acc[3]*SCALE};
        *(float2*)&sc[(row+8)*SCS + col] = v1;
    }
    __syncthreads();

    // prefetch V stages 0,1 -> overlaps softmax
    load_v(0, 0); CP_COMMIT();
    load_v(1, 1); CP_COMMIT();

    // ---- softmax: 8 warps x 4 rows, register-resident ----
    #pragma unroll
    for (int rr = 0; rr < 4; rr++) {
        const int r = warp*4 + rr;
        float ev[18];
        #pragma unroll
        for (int jj = 0; jj < 18; jj++) ev[jj] = sc[r*SCS + lane + 32*jj];
        float mx = ev[0];
        #pragma unroll
        for (int jj = 1; jj < 18; jj++) mx = fmaxf(mx, ev[jj]);
        #pragma unroll
        for (int o = 16; o; o >>= 1) mx = fmaxf(mx, __shfl_xor_sync(0xffffffffu, mx, o));
        float sum = 0.f;
        #pragma unroll
        for (int jj = 0; jj < 18; jj++) {
            ev[jj] = __expf(ev[jj] - mx);
            sum += ev[jj];
        }
        #pragma unroll
        for (int o = 16; o; o >>= 1) sum += __shfl_xor_sync(0xffffffffu, sum, o);
        float inv = 1.f / sum;
        float* dst = attn + (((size_t)b*HH + h)*SS + s0 + r) * (size_t)SS;
        #pragma unroll
        for (int jj = 0; jj < 18; jj++) {
            float p = ev[jj] * inv;
            __stcs(dst + lane + 32*jj, p);        // streaming: attn is write-only
            sc[r*SCS + lane + 32*jj] = rna_tf32(p);
        }
    }
    __syncthreads();

    // ---- AV: (Nm,Nn,Nk)=(1,2,4), 18 stages, 3 buffers, 1 barrier/stage ----
    const int wn = warp & 1;
    const int wk = warp >> 1;

    float acc[2][4][4];
    #pragma unroll
    for (int i = 0; i < 2; i++)
        #pragma unroll
        for (int j = 0; j < 4; j++)
            #pragma unroll
            for (int r = 0; r < 4; r++) acc[i][j][r] = 0.f;

    for (int kt = 0; kt < NSTAGE; kt++) {
        CP_WAIT1();
        __syncthreads();
        if (kt + 2 < NSTAGE) load_v((kt + 2) % 3, kt + 2);
        CP_COMMIT();

        const float* vs = kv + (kt % 3) * KVPITCH;
        const int k = wk * 8;

        uint32_t a[2][4];
        #pragma unroll
        for (int ms = 0; ms < 2; ms++)
            ldsm_x4(a[ms][0], a[ms][1], a[ms][2], a[ms][3],
                    sc + ms*16*SCS + kt*32 + k + laneAS);
        #pragma unroll
        for (int ns = 0; ns < 4; ns++) {
            int nb = wn*32 + ns*8;
            uint32_t b0 = __float_as_uint(vs[(k + t)*VSS + nb + g]);
            uint32_t b1 = __float_as_uint(vs[(k + t + 4)*VSS + nb + g]);
            #pragma unroll
            for (int ms = 0; ms < 2; ms++)
                mma_tf32(acc[ms][ns], a[ms][0], a[ms][1], a[ms][2], a[ms][3],
                         b0, b1);
        }
    }

    // ---- reduce 4 k-partials through smem ----
    __syncthreads();
    float* red = sc;   // [4][32][RST]
    #pragma unroll
    for (int ms = 0; ms < 2; ms++) {
        #pragma unroll
        for (int ns = 0; ns < 4; ns++) {
            int col = wn*32 + ns*8 + 2*t;
            float2 v0 = {acc[ms][ns][0], acc[ms][ns][1]};
            *(float2*)&red[wk*32*RST + (ms*16 + g)*RST + col] = v0;
            float2 v1 = {acc[ms][ns][2], acc[ms][ns][3]};
            *(float2*)&red[wk*32*RST + (ms*16 + g + 8)*RST + col] = v1;
        }
    }
    __syncthreads();

    #pragma unroll
    for (int i = 0; i < 2; i++) {
        int f4 = tid + i*256;
        int row = f4 >> 4, c4 = f4 & 15;
        const float* p0 = red + row*RST + c4*4;
        float4 s0v = *(const float4*)(p0);
        float4 s1v = *(const float4*)(p0 + 32*RST);
        float4 s2v = *(const float4*)(p0 + 64*RST);
        float4 s3v = *(const float4*)(p0 + 96*RST);
        float4 o;
        o.x = rna_tf32(s0v.x + s1v.x + s2v.x + s3v.x);
        o.y = rna_tf32(s0v.y + s1v.y + s2v.y + s3v.y);
        o.z = rna_tf32(s0v.z + s1v.z + s2v.z + s3v.z);
        o.w = rna_tf32(s0v.w + s1v.w + s2v.w + s3v.w);
        *(float4*)&ctx[((size_t)(b*SS + s0 + row))*DD + h*HDD + c4*4] = o;
    }
}

// ===========================================================================
extern "C" void kernel_launch(void* const* d_in, const int* in_sizes, int n_in,
                              void* d_out, int out_size)
{
    const float* x  = (const float*)d_in[0];
    const float* Wq = (const float*)d_in[1];
    const float* bq = (const float*)d_in[2];
    const float* Wk = (const float*)d_in[3];
    const float* bk = (const float*)d_in[4];
    const float* Wv = (const float*)d_in[5];
    const float* bv = (const float*)d_in[6];
    const float* Wo = (const float*)d_in[7];
    const float* bo = (const float*)d_in[8];

    float* out = (float*)d_out;
    float* attn;
    if (out_size >= OUT_ELEMS + ATTN_ELEMS) {
        attn = out + OUT_ELEMS;
    } else {
        void* p; cudaGetSymbolAddress(&p, g_attn_fallback);
        attn = (float*)p;
    }

    float *q, *k, *v, *ctx, *xr;
    { void* p; cudaGetSymbolAddress(&p, g_q);   q   = (float*)p; }
    { void* p; cudaGetSymbolAddress(&p, g_k);   k   = (float*)p; }
    { void* p; cudaGetSymbolAddress(&p, g_v);   v   = (float*)p; }
    { void* p; cudaGetSymbolAddress(&p, g_ctx); ctx = (float*)p; }
    { void* p; cudaGetSymbolAddress(&p, g_xr);  xr  = (float*)p; }

    const int gemm_smem = 3 * GST * (int)sizeof(float);          // 110592
    cudaFuncSetAttribute(gemm_qkv,
                         cudaFuncAttributeMaxDynamicSharedMemorySize, gemm_smem);
    cudaFuncSetAttribute(gemm_single,
                         cudaFuncAttributeMaxDynamicSharedMemorySize, gemm_smem);
    const int attn_smem = ATTN_SMEM_FLOATS * (int)sizeof(float); // 110592
    cudaFuncSetAttribute(attn_fused,
                         cudaFuncAttributeMaxDynamicSharedMemorySize, attn_smem);

    // 1) tf32 pre-rounding of x only (W rounded in-kernel on B fragments)
    round_tf32_kernel<<<1184, 256>>>(x, xr, OUT_ELEMS/4);

    // 2) fused Q/K/V projections (outputs rna-rounded to tf32)
    dim3 gQKV(DD/128, MTOK/128, 3);
    gemm_qkv<<<gQKV, 256, gemm_smem>>>(xr, Wq, Wk, Wv, bq, bk, bv, q, k, v);

    // 3) fused scores + softmax + AV
    dim3 gAttn(SS/QROWS, HH, BB);         // (18, 12, 32)
    attn_fused<<<gAttn, 256, attn_smem>>>(q, k, v, attn, ctx);

    // 4) output projection
    dim3 gO(DD/128, MTOK/128);
    gemm_single<<<gO, 256, gemm_smem>>>(ctx, Wo, bo, out);
}

// round 12
// speedup vs baseline: 1.4254x; 1.0281x over previous
#include <cuda_runtime.h>
#include <cstdint>
#include <cstddef>

#define BB 32
#define SS 576
#define DD 768
#define HH 12
#define HDD 64
#define MTOK (BB*SS)               // 18432
#define OUT_ELEMS (BB*SS*DD)       // 14155776
#define ATTN_ELEMS (BB*HH*SS*SS)   // 127401984
#define SCALE 0.125f

// ---- scratch (static device globals; no runtime allocation) ----
__device__ float g_q[OUT_ELEMS];
__device__ float g_k[OUT_ELEMS];
__device__ float g_v[OUT_ELEMS];
__device__ float g_ctx[OUT_ELEMS];
__device__ float g_xr[OUT_ELEMS];
__device__ float g_wq[DD*DD], g_wk[DD*DD], g_wv[DD*DD], g_wo[DD*DD];
__device__ float g_attn_fallback[ATTN_ELEMS];

// ---------------------------------------------------------------------------
__device__ __forceinline__ float rna_tf32(float x) {
    unsigned u;
    asm("cvt.rna.tf32.f32 %0, %1;" : "=r"(u) : "f"(x));
    return __uint_as_float(u);
}

__device__ __forceinline__ void mma_tf32(float c[4],
    uint32_t a0, uint32_t a1, uint32_t a2, uint32_t a3,
    uint32_t b0, uint32_t b1)
{
    asm volatile(
        "mma.sync.aligned.m16n8k8.row.col.f32.tf32.tf32.f32 "
        "{%0,%1,%2,%3}, {%4,%5,%6,%7}, {%8,%9}, {%0,%1,%2,%3};"
        : "+f"(c[0]), "+f"(c[1]), "+f"(c[2]), "+f"(c[3])
        : "r"(a0), "r"(a1), "r"(a2), "r"(a3), "r"(b0), "r"(b1));
}

__device__ __forceinline__ void ldsm_x4(uint32_t& r0, uint32_t& r1,
                                        uint32_t& r2, uint32_t& r3,
                                        const void* p)
{
    uint32_t a = (uint32_t)__cvta_generic_to_shared(p);
    asm volatile("ldmatrix.sync.aligned.m8n8.x4.shared.b16 {%0,%1,%2,%3}, [%4];"
                 : "=r"(r0), "=r"(r1), "=r"(r2), "=r"(r3) : "r"(a));
}

__device__ __forceinline__ void cpa16(void* dst, const void* src) {
    uint32_t d = (uint32_t)__cvta_generic_to_shared(dst);
    asm volatile("cp.async.cg.shared.global [%0], [%1], 16;\n"
                 :: "r"(d), "l"(src));
}
#define CP_COMMIT() asm volatile("cp.async.commit_group;\n" ::)
#define CP_WAIT1()  asm volatile("cp.async.wait_group 1;\n" ::)
#define CP_WAIT2()  asm volatile("cp.async.wait_group 2;\n" ::)

// ---------------------------------------------------------------------------
__global__ void round_tf32_kernel(const float* __restrict__ in,
                                  float* __restrict__ out, int n4)
{
    for (int i = blockIdx.x * blockDim.x + threadIdx.x; i < n4;
         i += gridDim.x * blockDim.x) {
        float4 v = ((const float4*)in)[i];
        v.x = rna_tf32(v.x); v.y = rna_tf32(v.y);
        v.z = rna_tf32(v.z); v.w = rna_tf32(v.w);
        ((float4*)out)[i] = v;
    }
}

__global__ void round_w4_kernel(
    const float* __restrict__ w0, const float* __restrict__ w1,
    const float* __restrict__ w2, const float* __restrict__ w3,
    float* __restrict__ o0, float* __restrict__ o1,
    float* __restrict__ o2, float* __restrict__ o3, int n4)
{
    int z = blockIdx.y;
    const float* in = (z == 0) ? w0 : (z == 1) ? w1 : (z == 2) ? w2 : w3;
    float* out      = (z == 0) ? o0 : (z == 1) ? o1 : (z == 2) ? o2 : o3;
    for (int i = blockIdx.x * blockDim.x + threadIdx.x; i < n4;
         i += gridDim.x * blockDim.x) {
        float4 v = ((const float4*)in)[i];
        v.x = rna_tf32(v.x); v.y = rna_tf32(v.y);
        v.z = rna_tf32(v.z); v.w = rna_tf32(v.w);
        ((float4*)out)[i] = v;
    }
}

// ---------------------------------------------------------------------------
// GEMM: C[M,N] = A[M,K] @ W^T + bias.  A,W pre-rounded to tf32.
// BM=128, BN=128, BK=32, 256 threads, ldmatrix fragment loads,
// 3-stage cp.async pipeline, ONE __syncthreads per iteration
// (top barrier also orders previous-stage readers before buffer overwrite).
// ---------------------------------------------------------------------------
#define GST (2*128*36)   // floats per stage (A+B)

template <bool RND>
__device__ __forceinline__ void gemm_body(
    const float* __restrict__ A, const float* __restrict__ W,
    const float* __restrict__ bias, float* __restrict__ C,
    int N, int K)
{
    extern __shared__ float dsm[];

    const int tid = threadIdx.x;
    const int m0 = blockIdx.y * 128;
    const int n0 = blockIdx.x * 128;
    const int warp = tid >> 5;
    const int lane = tid & 31;
    const int g = lane >> 2;
    const int t = lane & 3;
    const int warpm = warp >> 2;  // 0..1
    const int warpn = warp & 3;   // 0..3

    const int laneA = (lane & 15) * 36 + ((lane >> 4) << 2);
    const int laneB = (((lane >> 4) << 3) + (lane & 7)) * 36 + (((lane >> 3) & 1) << 2);

    float acc[4][4][4];
    #pragma unroll
    for (int i = 0; i < 4; i++)
        #pragma unroll
        for (int j = 0; j < 4; j++)
            #pragma unroll
            for (int r = 0; r < 4; r++) acc[i][j][r] = 0.f;

    auto load_stage = [&](int st, int k0) {
        float* as = dsm + st * GST;
        float* bs = as + 128*36;
        #pragma unroll
        for (int i = 0; i < 4; i++) {
            int c = tid + i * 256;
            int row = c >> 3, seg = c & 7;
            cpa16(&as[row*36 + seg*4], &A[(size_t)(m0 + row) * K + k0 + seg*4]);
        }
        #pragma unroll
        for (int i = 0; i < 4; i++) {
            int c = tid + i * 256;
            int row = c >> 3, seg = c & 7;
            cpa16(&bs[row*36 + seg*4], &W[(size_t)(n0 + row) * K + k0 + seg*4]);
        }
    };

    const int iters = K / 32;            // 24
    load_stage(0, 0);  CP_COMMIT();
    load_stage(1, 32); CP_COMMIT();

    for (int it = 0; it < iters; ++it) {
        CP_WAIT1();
        __syncthreads();   // stage-it copies visible; prev-stage readers done
        if (it + 2 < iters) load_stage((it + 2) % 3, (it + 2) * 32);
        CP_COMMIT();

        const float* as = dsm + (it % 3) * GST;
        const float* bs = as + 128*36;
        #pragma unroll
        for (int ks = 0; ks < 4; ks++) {
            int k = ks * 8;
            uint32_t af[4][4];
            #pragma unroll
            for (int ms = 0; ms < 4; ms++)
                ldsm_x4(af[ms][0], af[ms][1], af[ms][2], af[ms][3],
                        as + (warpm*64 + ms*16)*36 + k + laneA);
            #pragma unroll
            for (int pr = 0; pr < 2; pr++) {
                uint32_t b0, b1, b2, b3;
                ldsm_x4(b0, b1, b2, b3,
                        bs + (warpn*32 + pr*16)*36 + k + laneB);
                #pragma unroll
                for (int ms = 0; ms < 4; ms++) {
                    mma_tf32(acc[ms][2*pr],   af[ms][0], af[ms][1], af[ms][2],
                             af[ms][3], b0, b1);
                    mma_tf32(acc[ms][2*pr+1], af[ms][0], af[ms][1], af[ms][2],
                             af[ms][3], b2, b3);
                }
            }
        }
    }

    #pragma unroll
    for (int ms = 0; ms < 4; ms++) {
        int row0 = m0 + warpm*64 + ms*16 + g;
        #pragma unroll
        for (int ns = 0; ns < 4; ns++) {
            int col = n0 + warpn*32 + ns*8 + 2*t;
            float b0v = bias[col], b1v = bias[col + 1];
            float2 v0, v1;
            if (RND) {
                v0 = {rna_tf32(acc[ms][ns][0] + b0v), rna_tf32(acc[ms][ns][1] + b1v)};
                v1 = {rna_tf32(acc[ms][ns][2] + b0v), rna_tf32(acc[ms][ns][3] + b1v)};
            } else {
                v0 = {acc[ms][ns][0] + b0v, acc[ms][ns][1] + b1v};
                v1 = {acc[ms][ns][2] + b0v, acc[ms][ns][3] + b1v};
            }
            *(float2*)&C[(size_t)row0 * N + col] = v0;
            *(float2*)&C[(size_t)(row0 + 8) * N + col] = v1;
        }
    }
}

__global__ __launch_bounds__(256) void gemm_qkv(
    const float* __restrict__ A,
    const float* __restrict__ Wq, const float* __restrict__ Wk,
    const float* __restrict__ Wv,
    const float* __restrict__ bq, const float* __restrict__ bk,
    const float* __restrict__ bv,
    float* __restrict__ Cq, float* __restrict__ Ck, float* __restrict__ Cv)
{
    int z = blockIdx.z;
    const float* W    = (z == 0) ? Wq : (z == 1) ? Wk : Wv;
    const float* bias = (z == 0) ? bq : (z == 1) ? bk : bv;
    float*       C    = (z == 0) ? Cq : (z == 1) ? Ck : Cv;
    gemm_body<true>(A, W, bias, C, DD, DD);   // rna-rounded Q/K/V
}

__global__ __launch_bounds__(256) void gemm_single(
    const float* __restrict__ A, const float* __restrict__ W,
    const float* __restrict__ bias, float* __restrict__ C)
{
    gemm_body<false>(A, W, bias, C, DD, DD);
}

// ---------------------------------------------------------------------------
// Fused attention per (b, h, 32-query tile).  (R7 structure — proven.)
// scores: Q frags in registers, K frags via ldmatrix.x4 (2 k-steps per load).
// softmax: register-resident rows; attn written with streaming stores (.cs).
// AV: prob frags via ldmatrix.x4; warp grid (Nm,Nn,Nk)=(1,2,4);
//     4 k-partials reduced through smem; ctx float4.
// smem: qs[32][68] + kv[3][32*72] + sc[32][580] = 110592 B -> 2 CTA/SM.
// ---------------------------------------------------------------------------
#define SCQ 68
#define SCK 68
#define VSS 72
#define KVPITCH (32*72)
#define SCS 580
#define QROWS 32
#define NSTAGE (SS/32)  // 18
#define RST 72
#define ATTN_SMEM_FLOATS (QROWS*SCQ + 3*KVPITCH + QROWS*SCS)  // 27648

__global__ __launch_bounds__(256, 2) void attn_fused(
    const float* __restrict__ Q, const float* __restrict__ K,
    const float* __restrict__ V, float* __restrict__ attn,
    float* __restrict__ ctx)
{
    extern __shared__ float smem[];
    float* qs = smem;                         // [32][SCQ]
    float* kv = smem + QROWS*SCQ;             // 3 stage buffers
    float* sc = smem + QROWS*SCQ + 3*KVPITCH; // [32][SCS]; later red[4][32][RST]

    const int qt = blockIdx.x, h = blockIdx.y, b = blockIdx.z;
    const int s0 = qt * QROWS;
    const int tid = threadIdx.x;
    const int warp = tid >> 5;
    const int lane = tid & 31;
    const int g = lane >> 2, t = lane & 3;

    const size_t kvbase = (size_t)b * SS * DD + h * HDD;

    auto load_q = [&]() {
        #pragma unroll
        for (int i = 0; i < 2; i++) {
            int c = tid + i * 256;
            int qi = c >> 4, seg = c & 15;
            cpa16(&qs[qi*SCQ + seg*4],
                  &Q[kvbase + (size_t)(s0 + qi)*DD + seg*4]);
        }
    };
    auto load_k = [&](int st, int kt) {
        float* dst = kv + st * KVPITCH;
        #pragma unroll
        for (int i = 0; i < 2; i++) {
            int c = tid + i * 256;
            int row = c >> 4, seg = c & 15;
            cpa16(&dst[row*SCK + seg*4],
                  &K[kvbase + (size_t)(kt*32 + row)*DD + seg*4]);
        }
    };
    auto load_v = [&](int st, int kt) {
        float* dst = kv + st * KVPITCH;
        #pragma unroll
        for (int i = 0; i < 2; i++) {
            int c = tid + i * 256;
            int row = c >> 4, seg = c & 15;
            cpa16(&dst[row*VSS + seg*4],
                  &V[kvbase + (size_t)(kt*32 + row)*DD + seg*4]);
        }
    };

    load_q();     CP_COMMIT();
    load_k(0, 0); CP_COMMIT();
    load_k(1, 1); CP_COMMIT();

    // wait for Q group, then hoist Q fragments into registers
    CP_WAIT2();
    __syncthreads();
    const int warpm = warp >> 2;   // scores: 0..1
    const int warpn = warp & 3;    // scores: 0..3
    uint32_t qa[8][4];
    #pragma unroll
    for (int kk = 0; kk < 8; kk++) {
        const float* pa = qs + (warpm*16 + g)*SCQ + kk*8 + t;
        qa[kk][0] = __float_as_uint(pa[0]);
        qa[kk][1] = __float_as_uint(pa[8*SCQ]);
        qa[kk][2] = __float_as_uint(pa[4]);
        qa[kk][3] = __float_as_uint(pa[8*SCQ + 4]);
    }

    const int laneKB = (lane & 7) * SCK + ((lane >> 3) << 2);
    const int laneAS = (lane & 15) * SCS + ((lane >> 4) << 2);

    // ---- scores: QK^T into sc strip, 18 pipelined stages ----
    for (int kt = 0; kt < NSTAGE; kt++) {
        CP_WAIT1();
        __syncthreads();
        if (kt + 2 < NSTAGE) load_k((kt + 2) % 3, kt + 2);
        CP_COMMIT();

        const float* ks = kv + (kt % 3) * KVPITCH;
        float acc[4] = {0.f, 0.f, 0.f, 0.f};
        #pragma unroll
        for (int kk2 = 0; kk2 < 4; kk2++) {
            uint32_t b0, b1, b2, b3;
            ldsm_x4(b0, b1, b2, b3,
                    ks + warpn*8*SCK + kk2*16 + laneKB);
            mma_tf32(acc, qa[2*kk2][0], qa[2*kk2][1], qa[2*kk2][2],
                     qa[2*kk2][3], b0, b1);
            mma_tf32(acc, qa[2*kk2+1][0], qa[2*kk2+1][1], qa[2*kk2+1][2],
                     qa[2*kk2+1][3], b2, b3);
        }

        int row = warpm*16 + g;
        int col = kt*32 + warpn*8 + 2*t;
        float2 v0 = {acc[0]*SCALE, acc[1]*SCALE};
        *(float2*)&sc[row*SCS + col] = v0;
        float2 v1 = {acc[2]*SCALE, acc[3]*SCALE};
        *(float2*)&sc[(row+8)*SCS + col] = v1;
    }
    __syncthreads();

    // prefetch V stages 0,1 -> overlaps softmax
    load_v(0, 0); CP_COMMIT();
    load_v(1, 1); CP_COMMIT();

    // ---- softmax: 8 warps x 4 rows, register-resident ----
    #pragma unroll
    for (int rr = 0; rr < 4; rr++) {
        const int r = warp*4 + rr;
        float ev[18];
        #pragma unroll
        for (int jj = 0; jj < 18; jj++) ev[jj] = sc[r*SCS + lane + 32*jj];
        float mx = ev[0];
        #pragma unroll
        for (int jj = 1; jj < 18; jj++) mx = fmaxf(mx, ev[jj]);
        #pragma unroll
        for (int o = 16; o; o >>= 1) mx = fmaxf(mx, __shfl_xor_sync(0xffffffffu, mx, o));
        float sum = 0.f;
        #pragma unroll
        for (int jj = 0; jj < 18; jj++) {
            ev[jj] = __expf(ev[jj] - mx);
            sum += ev[jj];
        }
        #pragma unroll
        for (int o = 16; o; o >>= 1) sum += __shfl_xor_sync(0xffffffffu, sum, o);
        float inv = 1.f / sum;
        float* dst = attn + (((size_t)b*HH + h)*SS + s0 + r) * (size_t)SS;
        #pragma unroll
        for (int jj = 0; jj < 18; jj++) {
            float p = ev[jj] * inv;
            __stcs(dst + lane + 32*jj, p);        // streaming: attn is write-only
            sc[r*SCS + lane + 32*jj] = rna_tf32(p);
        }
    }
    __syncthreads();

    // ---- AV: (Nm,Nn,Nk)=(1,2,4), 18 stages, 3 buffers, 1 barrier/stage ----
    const int wn = warp & 1;
    const int wk = warp >> 1;

    float acc[2][4][4];
    #pragma unroll
    for (int i = 0; i < 2; i++)
        #pragma unroll
        for (int j = 0; j < 4; j++)
            #pragma unroll
            for (int r = 0; r < 4; r++) acc[i][j][r] = 0.f;

    for (int kt = 0; kt < NSTAGE; kt++) {
        CP_WAIT1();
        __syncthreads();
        if (kt + 2 < NSTAGE) load_v((kt + 2) % 3, kt + 2);
        CP_COMMIT();

        const float* vs = kv + (kt % 3) * KVPITCH;
        const int k = wk * 8;

        uint32_t a[2][4];
        #pragma unroll
        for (int ms = 0; ms < 2; ms++)
            ldsm_x4(a[ms][0], a[ms][1], a[ms][2], a[ms][3],
                    sc + ms*16*SCS + kt*32 + k + laneAS);
        #pragma unroll
        for (int ns = 0; ns < 4; ns++) {
            int nb = wn*32 + ns*8;
            uint32_t b0 = __float_as_uint(vs[(k + t)*VSS + nb + g]);
            uint32_t b1 = __float_as_uint(vs[(k + t + 4)*VSS + nb + g]);
            #pragma unroll
            for (int ms = 0; ms < 2; ms++)
                mma_tf32(acc[ms][ns], a[ms][0], a[ms][1], a[ms][2], a[ms][3],
                         b0, b1);
        }
    }

    // ---- reduce 4 k-partials through smem ----
    __syncthreads();
    float* red = sc;   // [4][32][RST]
    #pragma unroll
    for (int ms = 0; ms < 2; ms++) {
        #pragma unroll
        for (int ns = 0; ns < 4; ns++) {
            int col = wn*32 + ns*8 + 2*t;
            float2 v0 = {acc[ms][ns][0], acc[ms][ns][1]};
            *(float2*)&red[wk*32*RST + (ms*16 + g)*RST + col] = v0;
            float2 v1 = {acc[ms][ns][2], acc[ms][ns][3]};
            *(float2*)&red[wk*32*RST + (ms*16 + g + 8)*RST + col] = v1;
        }
    }
    __syncthreads();

    #pragma unroll
    for (int i = 0; i < 2; i++) {
        int f4 = tid + i*256;
        int row = f4 >> 4, c4 = f4 & 15;
        const float* p0 = red + row*RST + c4*4;
        float4 s0v = *(const float4*)(p0);
        float4 s1v = *(const float4*)(p0 + 32*RST);
        float4 s2v = *(const float4*)(p0 + 64*RST);
        float4 s3v = *(const float4*)(p0 + 96*RST);
        float4 o;
        o.x = rna_tf32(s0v.x + s1v.x + s2v.x + s3v.x);
        o.y = rna_tf32(s0v.y + s1v.y + s2v.y + s3v.y);
        o.z = rna_tf32(s0v.z + s1v.z + s2v.z + s3v.z);
        o.w = rna_tf32(s0v.w + s1v.w + s2v.w + s3v.w);
        *(float4*)&ctx[((size_t)(b*SS + s0 + row))*DD + h*HDD + c4*4] = o;
    }
}

// ===========================================================================
extern "C" void kernel_launch(void* const* d_in, const int* in_sizes, int n_in,
                              void* d_out, int out_size)
{
    const float* x  = (const float*)d_in[0];
    const float* Wq = (const float*)d_in[1];
    const float* bq = (const float*)d_in[2];
    const float* Wk = (const float*)d_in[3];
    const float* bk = (const float*)d_in[4];
    const float* Wv = (const float*)d_in[5];
    const float* bv = (const float*)d_in[6];
    const float* Wo = (const float*)d_in[7];
    const float* bo = (const float*)d_in[8];

    float* out = (float*)d_out;
    float* attn;
    if (out_size >= OUT_ELEMS + ATTN_ELEMS) {
        attn = out + OUT_ELEMS;
    } else {
        void* p; cudaGetSymbolAddress(&p, g_attn_fallback);
        attn = (float*)p;
    }

    float *q, *k, *v, *ctx, *xr, *wq, *wk, *wv, *wo;
    { void* p; cudaGetSymbolAddress(&p, g_q);   q   = (float*)p; }
    { void* p; cudaGetSymbolAddress(&p, g_k);   k   = (float*)p; }
    { void* p; cudaGetSymbolAddress(&p, g_v);   v   = (float*)p; }
    { void* p; cudaGetSymbolAddress(&p, g_ctx); ctx = (float*)p; }
    { void* p; cudaGetSymbolAddress(&p, g_xr);  xr  = (float*)p; }
    { void* p; cudaGetSymbolAddress(&p, g_wq);  wq  = (float*)p; }
    { void* p; cudaGetSymbolAddress(&p, g_wk);  wk  = (float*)p; }
    { void* p; cudaGetSymbolAddress(&p, g_wv);  wv  = (float*)p; }
    { void* p; cudaGetSymbolAddress(&p, g_wo);  wo  = (float*)p; }

    const int gemm_smem = 3 * GST * (int)sizeof(float);          // 110592
    cudaFuncSetAttribute(gemm_qkv,
                         cudaFuncAttributeMaxDynamicSharedMemorySize, gemm_smem);
    cudaFuncSetAttribute(gemm_single,
                         cudaFuncAttributeMaxDynamicSharedMemorySize, gemm_smem);
    const int attn_smem = ATTN_SMEM_FLOATS * (int)sizeof(float); // 110592
    cudaFuncSetAttribute(attn_fused,
                         cudaFuncAttributeMaxDynamicSharedMemorySize, attn_smem);

    // 1) tf32 pre-rounding (x and all four W)
    round_tf32_kernel<<<1184, 256>>>(x, xr, OUT_ELEMS/4);
    dim3 gW(288, 4);
    round_w4_kernel<<<gW, 256>>>(Wq, Wk, Wv, Wo, wq, wk, wv, wo, (DD*DD)/4);

    // 2) fused Q/K/V projections (outputs rna-rounded to tf32)
    dim3 gQKV(DD/128, MTOK/128, 3);
    gemm_qkv<<<gQKV, 256, gemm_smem>>>(xr, wq, wk, wv, bq, bk, bv, q, k, v);

    // 3) fused scores + softmax + AV
    dim3 gAttn(SS/QROWS, HH, BB);         // (18, 12, 32)
    attn_fused<<<gAttn, 256, attn_smem>>>(q, k, v, attn, ctx);

    // 4) output projection
    dim3 gO(DD/128, MTOK/128);
    gemm_single<<<gO, 256, gemm_smem>>>(ctx, wo, bo, out);
}

// round 13
// speedup vs baseline: 1.4380x; 1.0088x over previous
#include <cuda_runtime.h>
#include <cstdint>
#include <cstddef>

#define BB 32
#define SS 576
#define DD 768
#define HH 12
#define HDD 64
#define MTOK (BB*SS)               // 18432
#define OUT_ELEMS (BB*SS*DD)       // 14155776
#define ATTN_ELEMS (BB*HH*SS*SS)   // 127401984
#define SCALE 0.125f

// ---- scratch (static device globals; no runtime allocation) ----
__device__ float g_q[OUT_ELEMS];
__device__ float g_k[OUT_ELEMS];
__device__ float g_v[OUT_ELEMS];
__device__ float g_ctx[OUT_ELEMS];
__device__ float g_xr[OUT_ELEMS];
__device__ float g_wq[DD*DD], g_wk[DD*DD], g_wv[DD*DD], g_wo[DD*DD];
__device__ float g_attn_fallback[ATTN_ELEMS];

// ---------------------------------------------------------------------------
__device__ __forceinline__ float rna_tf32(float x) {
    unsigned u;
    asm("cvt.rna.tf32.f32 %0, %1;" : "=r"(u) : "f"(x));
    return __uint_as_float(u);
}

__device__ __forceinline__ void mma_tf32(float c[4],
    uint32_t a0, uint32_t a1, uint32_t a2, uint32_t a3,
    uint32_t b0, uint32_t b1)
{
    asm volatile(
        "mma.sync.aligned.m16n8k8.row.col.f32.tf32.tf32.f32 "
        "{%0,%1,%2,%3}, {%4,%5,%6,%7}, {%8,%9}, {%0,%1,%2,%3};"
        : "+f"(c[0]), "+f"(c[1]), "+f"(c[2]), "+f"(c[3])
        : "r"(a0), "r"(a1), "r"(a2), "r"(a3), "r"(b0), "r"(b1));
}

__device__ __forceinline__ void ldsm_x4(uint32_t& r0, uint32_t& r1,
                                        uint32_t& r2, uint32_t& r3,
                                        const void* p)
{
    uint32_t a = (uint32_t)__cvta_generic_to_shared(p);
    asm volatile("ldmatrix.sync.aligned.m8n8.x4.shared.b16 {%0,%1,%2,%3}, [%4];"
                 : "=r"(r0), "=r"(r1), "=r"(r2), "=r"(r3) : "r"(a));
}

__device__ __forceinline__ void cpa16(void* dst, const void* src) {
    uint32_t d = (uint32_t)__cvta_generic_to_shared(dst);
    asm volatile("cp.async.cg.shared.global [%0], [%1], 16;\n"
                 :: "r"(d), "l"(src));
}
#define CP_COMMIT() asm volatile("cp.async.commit_group;\n" ::)
#define CP_WAIT1()  asm volatile("cp.async.wait_group 1;\n" ::)
#define CP_WAIT2()  asm volatile("cp.async.wait_group 2;\n" ::)

// ---------------------------------------------------------------------------
__global__ void round_tf32_kernel(const float* __restrict__ in,
                                  float* __restrict__ out, int n4)
{
    for (int i = blockIdx.x * blockDim.x + threadIdx.x; i < n4;
         i += gridDim.x * blockDim.x) {
        float4 v = ((const float4*)in)[i];
        v.x = rna_tf32(v.x); v.y = rna_tf32(v.y);
        v.z = rna_tf32(v.z); v.w = rna_tf32(v.w);
        ((float4*)out)[i] = v;
    }
}

__global__ void round_w4_kernel(
    const float* __restrict__ w0, const float* __restrict__ w1,
    const float* __restrict__ w2, const float* __restrict__ w3,
    float* __restrict__ o0, float* __restrict__ o1,
    float* __restrict__ o2, float* __restrict__ o3, int n4)
{
    int z = blockIdx.y;
    const float* in = (z == 0) ? w0 : (z == 1) ? w1 : (z == 2) ? w2 : w3;
    float* out      = (z == 0) ? o0 : (z == 1) ? o1 : (z == 2) ? o2 : o3;
    for (int i = blockIdx.x * blockDim.x + threadIdx.x; i < n4;
         i += gridDim.x * blockDim.x) {
        float4 v = ((const float4*)in)[i];
        v.x = rna_tf32(v.x); v.y = rna_tf32(v.y);
        v.z = rna_tf32(v.z); v.w = rna_tf32(v.w);
        ((float4*)out)[i] = v;
    }
}

// ---------------------------------------------------------------------------
// GEMM: C[M,N] = A[M,K] @ W^T + bias.  A,W pre-rounded to tf32.
// BM=128, BN=128, BK=32, 256 threads, ldmatrix fragment loads with
// EXPLICIT fragment double-buffering (ks+1 frags loaded before ks mma),
// 3-stage cp.async pipeline, one __syncthreads per iteration.
// ---------------------------------------------------------------------------
#define GST (2*128*36)   // floats per stage (A+B)

template <bool RND>
__device__ __forceinline__ void gemm_body(
    const float* __restrict__ A, const float* __restrict__ W,
    const float* __restrict__ bias, float* __restrict__ C,
    int N, int K)
{
    extern __shared__ float dsm[];

    const int tid = threadIdx.x;
    const int m0 = blockIdx.y * 128;
    const int n0 = blockIdx.x * 128;
    const int warp = tid >> 5;
    const int lane = tid & 31;
    const int g = lane >> 2;
    const int t = lane & 3;
    const int warpm = warp >> 2;  // 0..1
    const int warpn = warp & 3;   // 0..3

    const int laneA = (lane & 15) * 36 + ((lane >> 4) << 2);
    const int laneB = (((lane >> 4) << 3) + (lane & 7)) * 36 + (((lane >> 3) & 1) << 2);

    float acc[4][4][4];
    #pragma unroll
    for (int i = 0; i < 4; i++)
        #pragma unroll
        for (int j = 0; j < 4; j++)
            #pragma unroll
            for (int r = 0; r < 4; r++) acc[i][j][r] = 0.f;

    auto load_stage = [&](int st, int k0) {
        float* as = dsm + st * GST;
        float* bs = as + 128*36;
        #pragma unroll
        for (int i = 0; i < 4; i++) {
            int c = tid + i * 256;
            int row = c >> 3, seg = c & 7;
            cpa16(&as[row*36 + seg*4], &A[(size_t)(m0 + row) * K + k0 + seg*4]);
        }
        #pragma unroll
        for (int i = 0; i < 4; i++) {
            int c = tid + i * 256;
            int row = c >> 3, seg = c & 7;
            cpa16(&bs[row*36 + seg*4], &W[(size_t)(n0 + row) * K + k0 + seg*4]);
        }
    };

    const int iters = K / 32;            // 24
    load_stage(0, 0);  CP_COMMIT();
    load_stage(1, 32); CP_COMMIT();

    uint32_t af[2][4][4];   // [buf][ms][frag]
    uint32_t bf[2][2][4];   // [buf][pr][frag]  (pr covers 2 octets each)

    for (int it = 0; it < iters; ++it) {
        CP_WAIT1();
        __syncthreads();   // stage-it copies visible; prev-stage readers done
        if (it + 2 < iters) load_stage((it + 2) % 3, (it + 2) * 32);
        CP_COMMIT();

        const float* as = dsm + (it % 3) * GST;
        const float* bs = as + 128*36;

        // preload ks=0 fragments
        #pragma unroll
        for (int ms = 0; ms < 4; ms++)
            ldsm_x4(af[0][ms][0], af[0][ms][1], af[0][ms][2], af[0][ms][3],
                    as + (warpm*64 + ms*16)*36 + laneA);
        #pragma unroll
        for (int pr = 0; pr < 2; pr++)
            ldsm_x4(bf[0][pr][0], bf[0][pr][1], bf[0][pr][2], bf[0][pr][3],
                    bs + (warpn*32 + pr*16)*36 + laneB);

        #pragma unroll
        for (int ks = 0; ks < 4; ks++) {
            int cur = ks & 1, nxt = cur ^ 1;
            if (ks + 1 < 4) {
                int k = (ks + 1) * 8;
                #pragma unroll
                for (int ms = 0; ms < 4; ms++)
                    ldsm_x4(af[nxt][ms][0], af[nxt][ms][1], af[nxt][ms][2],
                            af[nxt][ms][3],
                            as + (warpm*64 + ms*16)*36 + k + laneA);
                #pragma unroll
                for (int pr = 0; pr < 2; pr++)
                    ldsm_x4(bf[nxt][pr][0], bf[nxt][pr][1], bf[nxt][pr][2],
                            bf[nxt][pr][3],
                            bs + (warpn*32 + pr*16)*36 + k + laneB);
            }
            #pragma unroll
            for (int pr = 0; pr < 2; pr++) {
                #pragma unroll
                for (int ms = 0; ms < 4; ms++) {
                    mma_tf32(acc[ms][2*pr],   af[cur][ms][0], af[cur][ms][1],
                             af[cur][ms][2], af[cur][ms][3],
                             bf[cur][pr][0], bf[cur][pr][1]);
                    mma_tf32(acc[ms][2*pr+1], af[cur][ms][0], af[cur][ms][1],
                             af[cur][ms][2], af[cur][ms][3],
                             bf[cur][pr][2], bf[cur][pr][3]);
                }
            }
        }
    }

    #pragma unroll
    for (int ms = 0; ms < 4; ms++) {
        int row0 = m0 + warpm*64 + ms*16 + g;
        #pragma unroll
        for (int ns = 0; ns < 4; ns++) {
            int col = n0 + warpn*32 + ns*8 + 2*t;
            float b0v = bias[col], b1v = bias[col + 1];
            float2 v0, v1;
            if (RND) {
                v0 = {rna_tf32(acc[ms][ns][0] + b0v), rna_tf32(acc[ms][ns][1] + b1v)};
                v1 = {rna_tf32(acc[ms][ns][2] + b0v), rna_tf32(acc[ms][ns][3] + b1v)};
            } else {
                v0 = {acc[ms][ns][0] + b0v, acc[ms][ns][1] + b1v};
                v1 = {acc[ms][ns][2] + b0v, acc[ms][ns][3] + b1v};
            }
            *(float2*)&C[(size_t)row0 * N + col] = v0;
            *(float2*)&C[(size_t)(row0 + 8) * N + col] = v1;
        }
    }
}

__global__ __launch_bounds__(256, 2) void gemm_qkv(
    const float* __restrict__ A,
    const float* __restrict__ Wq, const float* __restrict__ Wk,
    const float* __restrict__ Wv,
    const float* __restrict__ bq, const float* __restrict__ bk,
    const float* __restrict__ bv,
    float* __restrict__ Cq, float* __restrict__ Ck, float* __restrict__ Cv)
{
    int z = blockIdx.z;
    const float* W    = (z == 0) ? Wq : (z == 1) ? Wk : Wv;
    const float* bias = (z == 0) ? bq : (z == 1) ? bk : bv;
    float*       C    = (z == 0) ? Cq : (z == 1) ? Ck : Cv;
    gemm_body<true>(A, W, bias, C, DD, DD);   // rna-rounded Q/K/V
}

__global__ __launch_bounds__(256, 2) void gemm_single(
    const float* __restrict__ A, const float* __restrict__ W,
    const float* __restrict__ bias, float* __restrict__ C)
{
    gemm_body<false>(A, W, bias, C, DD, DD);
}

// ---------------------------------------------------------------------------
// Fused attention per (b, h, 32-query tile).  (R7 structure — proven.)
// scores: Q frags in registers, K frags via ldmatrix.x4 (2 k-steps per load).
// softmax: register-resident rows; attn written with streaming stores (.cs).
// AV: prob frags via ldmatrix.x4; warp grid (Nm,Nn,Nk)=(1,2,4);
//     4 k-partials reduced through smem; ctx float4.
// smem: qs[32][68] + kv[3][32*72] + sc[32][580] = 110592 B -> 2 CTA/SM.
// ---------------------------------------------------------------------------
#define SCQ 68
#define SCK 68
#define VSS 72
#define KVPITCH (32*72)
#define SCS 580
#define QROWS 32
#define NSTAGE (SS/32)  // 18
#define RST 72
#define ATTN_SMEM_FLOATS (QROWS*SCQ + 3*KVPITCH + QROWS*SCS)  // 27648

__global__ __launch_bounds__(256, 2) void attn_fused(
    const float* __restrict__ Q, const float* __restrict__ K,
    const float* __restrict__ V, float* __restrict__ attn,
    float* __restrict__ ctx)
{
    extern __shared__ float smem[];
    float* qs = smem;                         // [32][SCQ]
    float* kv = smem + QROWS*SCQ;             // 3 stage buffers
    float* sc = smem + QROWS*SCQ + 3*KVPITCH; // [32][SCS]; later red[4][32][RST]

    const int qt = blockIdx.x, h = blockIdx.y, b = blockIdx.z;
    const int s0 = qt * QROWS;
    const int tid = threadIdx.x;
    const int warp = tid >> 5;
    const int lane = tid & 31;
    const int g = lane >> 2, t = lane & 3;

    const size_t kvbase = (size_t)b * SS * DD + h * HDD;

    auto load_q = [&]() {
        #pragma unroll
        for (int i = 0; i < 2; i++) {
            int c = tid + i * 256;
            int qi = c >> 4, seg = c & 15;
            cpa16(&qs[qi*SCQ + seg*4],
                  &Q[kvbase + (size_t)(s0 + qi)*DD + seg*4]);
        }
    };
    auto load_k = [&](int st, int kt) {
        float* dst = kv + st * KVPITCH;
        #pragma unroll
        for (int i = 0; i < 2; i++) {
            int c = tid + i * 256;
            int row = c >> 4, seg = c & 15;
            cpa16(&dst[row*SCK + seg*4],
                  &K[kvbase + (size_t)(kt*32 + row)*DD + seg*4]);
        }
    };
    auto load_v = [&](int st, int kt) {
        float* dst = kv + st * KVPITCH;
        #pragma unroll
        for (int i = 0; i < 2; i++) {
            int c = tid + i * 256;
            int row = c >> 4, seg = c & 15;
            cpa16(&dst[row*VSS + seg*4],
                  &V[kvbase + (size_t)(kt*32 + row)*DD + seg*4]);
        }
    };

    load_q();     CP_COMMIT();
    load_k(0, 0); CP_COMMIT();
    load_k(1, 1); CP_COMMIT();

    // wait for Q group, then hoist Q fragments into registers
    CP_WAIT2();
    __syncthreads();
    const int warpm = warp >> 2;   // scores: 0..1
    const int warpn = warp & 3;    // scores: 0..3
    uint32_t qa[8][4];
    #pragma unroll
    for (int kk = 0; kk < 8; kk++) {
        const float* pa = qs + (warpm*16 + g)*SCQ + kk*8 + t;
        qa[kk][0] = __float_as_uint(pa[0]);
        qa[kk][1] = __float_as_uint(pa[8*SCQ]);
        qa[kk][2] = __float_as_uint(pa[4]);
        qa[kk][3] = __float_as_uint(pa[8*SCQ + 4]);
    }

    const int laneKB = (lane & 7) * SCK + ((lane >> 3) << 2);
    const int laneAS = (lane & 15) * SCS + ((lane >> 4) << 2);

    // ---- scores: QK^T into sc strip, 18 pipelined stages ----
    for (int kt = 0; kt < NSTAGE; kt++) {
        CP_WAIT1();
        __syncthreads();
        if (kt + 2 < NSTAGE) load_k((kt + 2) % 3, kt + 2);
        CP_COMMIT();

        const float* ks = kv + (kt % 3) * KVPITCH;
        float acc[4] = {0.f, 0.f, 0.f, 0.f};
        #pragma unroll
        for (int kk2 = 0; kk2 < 4; kk2++) {
            uint32_t b0, b1, b2, b3;
            ldsm_x4(b0, b1, b2, b3,
                    ks + warpn*8*SCK + kk2*16 + laneKB);
            mma_tf32(acc, qa[2*kk2][0], qa[2*kk2][1], qa[2*kk2][2],
                     qa[2*kk2][3], b0, b1);
            mma_tf32(acc, qa[2*kk2+1][0], qa[2*kk2+1][1], qa[2*kk2+1][2],
                     qa[2*kk2+1][3], b2, b3);
        }

        int row = warpm*16 + g;
        int col = kt*32 + warpn*8 + 2*t;
        float2 v0 = {acc[0]*SCALE, acc[1]*SCALE};
        *(float2*)&sc[row*SCS + col] = v0;
        float2 v1 = {acc[2]*SCALE, acc[3]*SCALE};
        *(float2*)&sc[(row+8)*SCS + col] = v1;
    }
    __syncthreads();

    // prefetch V stages 0,1 -> overlaps softmax
    load_v(0, 0); CP_COMMIT();
    load_v(1, 1); CP_COMMIT();

    // ---- softmax: 8 warps x 4 rows, register-resident ----
    #pragma unroll
    for (int rr = 0; rr < 4; rr++) {
        const int r = warp*4 + rr;
        float ev[18];
        #pragma unroll
        for (int jj = 0; jj < 18; jj++) ev[jj] = sc[r*SCS + lane + 32*jj];
        float mx = ev[0];
        #pragma unroll
        for (int jj = 1; jj < 18; jj++) mx = fmaxf(mx, ev[jj]);
        #pragma unroll
        for (int o = 16; o; o >>= 1) mx = fmaxf(mx, __shfl_xor_sync(0xffffffffu, mx, o));
        float sum = 0.f;
        #pragma unroll
        for (int jj = 0; jj < 18; jj++) {
            ev[jj] = __expf(ev[jj] - mx);
            sum += ev[jj];
        }
        #pragma unroll
        for (int o = 16; o; o >>= 1) sum += __shfl_xor_sync(0xffffffffu, sum, o);
        float inv = 1.f / sum;
        float* dst = attn + (((size_t)b*HH + h)*SS + s0 + r) * (size_t)SS;
        #pragma unroll
        for (int jj = 0; jj < 18; jj++) {
            float p = ev[jj] * inv;
            __stcs(dst + lane + 32*jj, p);        // streaming: attn is write-only
            sc[r*SCS + lane + 32*jj] = rna_tf32(p);
        }
    }
    __syncthreads();

    // ---- AV: (Nm,Nn,Nk)=(1,2,4), 18 stages, 3 buffers, 1 barrier/stage ----
    const int wn = warp & 1;
    const int wk = warp >> 1;

    float acc[2][4][4];
    #pragma unroll
    for (int i = 0; i < 2; i++)
        #pragma unroll
        for (int j = 0; j < 4; j++)
            #pragma unroll
            for (int r = 0; r < 4; r++) acc[i][j][r] = 0.f;

    for (int kt = 0; kt < NSTAGE; kt++) {
        CP_WAIT1();
        __syncthreads();
        if (kt + 2 < NSTAGE) load_v((kt + 2) % 3, kt + 2);
        CP_COMMIT();

        const float* vs = kv + (kt % 3) * KVPITCH;
        const int k = wk * 8;

        uint32_t a[2][4];
        #pragma unroll
        for (int ms = 0; ms < 2; ms++)
            ldsm_x4(a[ms][0], a[ms][1], a[ms][2], a[ms][3],
                    sc + ms*16*SCS + kt*32 + k + laneAS);
        #pragma unroll
        for (int ns = 0; ns < 4; ns++) {
            int nb = wn*32 + ns*8;
            uint32_t b0 = __float_as_uint(vs[(k + t)*VSS + nb + g]);
            uint32_t b1 = __float_as_uint(vs[(k + t + 4)*VSS + nb + g]);
            #pragma unroll
            for (int ms = 0; ms < 2; ms++)
                mma_tf32(acc[ms][ns], a[ms][0], a[ms][1], a[ms][2], a[ms][3],
                         b0, b1);
        }
    }

    // ---- reduce 4 k-partials through smem ----
    __syncthreads();
    float* red = sc;   // [4][32][RST]
    #pragma unroll
    for (int ms = 0; ms < 2; ms++) {
        #pragma unroll
        for (int ns = 0; ns < 4; ns++) {
            int col = wn*32 + ns*8 + 2*t;
            float2 v0 = {acc[ms][ns][0], acc[ms][ns][1]};
            *(float2*)&red[wk*32*RST + (ms*16 + g)*RST + col] = v0;
            float2 v1 = {acc[ms][ns][2], acc[ms][ns][3]};
            *(float2*)&red[wk*32*RST + (ms*16 + g + 8)*RST + col] = v1;
        }
    }
    __syncthreads();

    #pragma unroll
    for (int i = 0; i < 2; i++) {
        int f4 = tid + i*256;
        int row = f4 >> 4, c4 = f4 & 15;
        const float* p0 = red + row*RST + c4*4;
        float4 s0v = *(const float4*)(p0);
        float4 s1v = *(const float4*)(p0 + 32*RST);
        float4 s2v = *(const float4*)(p0 + 64*RST);
        float4 s3v = *(const float4*)(p0 + 96*RST);
        float4 o;
        o.x = rna_tf32(s0v.x + s1v.x + s2v.x + s3v.x);
        o.y = rna_tf32(s0v.y + s1v.y + s2v.y + s3v.y);
        o.z = rna_tf32(s0v.z + s1v.z + s2v.z + s3v.z);
        o.w = rna_tf32(s0v.w + s1v.w + s2v.w + s3v.w);
        *(float4*)&ctx[((size_t)(b*SS + s0 + row))*DD + h*HDD + c4*4] = o;
    }
}

// ===========================================================================
extern "C" void kernel_launch(void* const* d_in, const int* in_sizes, int n_in,
                              void* d_out, int out_size)
{
    const float* x  = (const float*)d_in[0];
    const float* Wq = (const float*)d_in[1];
    const float* bq = (const float*)d_in[2];
    const float* Wk = (const float*)d_in[3];
    const float* bk = (const float*)d_in[4];
    const float* Wv = (const float*)d_in[5];
    const float* bv = (const float*)d_in[6];
    const float* Wo = (const float*)d_in[7];
    const float* bo = (const float*)d_in[8];

    float* out = (float*)d_out;
    float* attn;
    if (out_size >= OUT_ELEMS + ATTN_ELEMS) {
        attn = out + OUT_ELEMS;
    } else {
        void* p; cudaGetSymbolAddress(&p, g_attn_fallback);
        attn = (float*)p;
    }

    float *q, *k, *v, *ctx, *xr, *wq, *wk, *wv, *wo;
    { void* p; cudaGetSymbolAddress(&p, g_q);   q   = (float*)p; }
    { void* p; cudaGetSymbolAddress(&p, g_k);   k   = (float*)p; }
    { void* p; cudaGetSymbolAddress(&p, g_v);   v   = (float*)p; }
    { void* p; cudaGetSymbolAddress(&p, g_ctx); ctx = (float*)p; }
    { void* p; cudaGetSymbolAddress(&p, g_xr);  xr  = (float*)p; }
    { void* p; cudaGetSymbolAddress(&p, g_wq);  wq  = (float*)p; }
    { void* p; cudaGetSymbolAddress(&p, g_wk);  wk  = (float*)p; }
    { void* p; cudaGetSymbolAddress(&p, g_wv);  wv  = (float*)p; }
    { void* p; cudaGetSymbolAddress(&p, g_wo);  wo  = (float*)p; }

    const int gemm_smem = 3 * GST * (int)sizeof(float);          // 110592
    cudaFuncSetAttribute(gemm_qkv,
                         cudaFuncAttributeMaxDynamicSharedMemorySize, gemm_smem);
    cudaFuncSetAttribute(gemm_single,
                         cudaFuncAttributeMaxDynamicSharedMemorySize, gemm_smem);
    const int attn_smem = ATTN_SMEM_FLOATS * (int)sizeof(float); // 110592
    cudaFuncSetAttribute(attn_fused,
                         cudaFuncAttributeMaxDynamicSharedMemorySize, attn_smem);

    // 1) tf32 pre-rounding (x and all four W)
    round_tf32_kernel<<<1184, 256>>>(x, xr, OUT_ELEMS/4);
    dim3 gW(288, 4);
    round_w4_kernel<<<gW, 256>>>(Wq, Wk, Wv, Wo, wq, wk, wv, wo, (DD*DD)/4);

    // 2) fused Q/K/V projections (outputs rna-rounded to tf32)
    dim3 gQKV(DD/128, MTOK/128, 3);
    gemm_qkv<<<gQKV, 256, gemm_smem>>>(xr, wq, wk, wv, bq, bk, bv, q, k, v);

    // 3) fused scores + softmax + AV
    dim3 gAttn(SS/QROWS, HH, BB);         // (18, 12, 32)
    attn_fused<<<gAttn, 256, attn_smem>>>(q, k, v, attn, ctx);

    // 4) output projection
    dim3 gO(DD/128, MTOK/128);
    gemm_single<<<gO, 256, gemm_smem>>>(ctx, wo, bo, out);
}